// round 7
// baseline (speedup 1.0000x reference)
#include <cuda_runtime.h>
#include <cuda_fp16.h>

#define N_NODES 100000
#define N_EDGES 1600000
#define N_FEAT  256
#define N_HID   64
#define N_CLS   16

#define SCAN_BLK  512
#define SCAN_NBLK ((N_NODES + SCAN_BLK - 1) / SCAN_BLK)   // 196

// ---------------- scratch (device globals: allocation-free, graph-safe) ----
__device__ __half2 g_h0h[N_NODES * (N_HID / 2)];  // x@W1+b1 in fp16 pairs
__device__ float   g_h2[N_NODES * N_CLS];         // relu(spmm1)@W2+b2
__device__ int     g_cnt[N_NODES];
__device__ int     g_scan[N_NODES];
__device__ int     g_blk[SCAN_NBLK];
__device__ int     g_ptr[N_NODES + 1];
__device__ int     g_cur[N_NODES];
__device__ int2    g_edge[N_EDGES];               // {col, float_bits(val)} by row

// ---------------------------------------------------------------------------
// CSR build
// ---------------------------------------------------------------------------
__global__ void k_zero_cnt() {
    int i = blockIdx.x * blockDim.x + threadIdx.x;
    if (i < N_NODES) g_cnt[i] = 0;
}

__global__ void k_hist(const int* __restrict__ row) {
    int e = blockIdx.x * blockDim.x + threadIdx.x;
    if (e < N_EDGES) atomicAdd(&g_cnt[row[e]], 1);
}

__global__ __launch_bounds__(SCAN_BLK) void k_scan1() {
    __shared__ int s[SCAN_BLK];
    int i = blockIdx.x * SCAN_BLK + threadIdx.x;
    int v = (i < N_NODES) ? g_cnt[i] : 0;
    s[threadIdx.x] = v;
    __syncthreads();
    for (int off = 1; off < SCAN_BLK; off <<= 1) {
        int t = (threadIdx.x >= off) ? s[threadIdx.x - off] : 0;
        __syncthreads();
        s[threadIdx.x] += t;
        __syncthreads();
    }
    if (i < N_NODES) g_scan[i] = s[threadIdx.x];
    if (threadIdx.x == SCAN_BLK - 1) g_blk[blockIdx.x] = s[threadIdx.x];
}

__global__ __launch_bounds__(SCAN_BLK) void k_scan3() {
    __shared__ int s[SCAN_BLK];
    int t = threadIdx.x;
    s[t] = (t < SCAN_NBLK && t < (int)blockIdx.x) ? g_blk[t] : 0;
    __syncthreads();
    for (int off = SCAN_BLK / 2; off; off >>= 1) {
        if (t < off) s[t] += s[t + off];
        __syncthreads();
    }
    int blkoff = s[0];
    int i = blockIdx.x * SCAN_BLK + t;
    if (i < N_NODES) {
        int excl = g_scan[i] - g_cnt[i] + blkoff;
        g_ptr[i] = excl;
        g_cur[i] = excl;
    }
    if (i == 0) g_ptr[N_NODES] = N_EDGES;
}

__global__ void k_scatter(const int* __restrict__ row, const int* __restrict__ col,
                          const float* __restrict__ vals) {
    int e = blockIdx.x * blockDim.x + threadIdx.x;
    if (e >= N_EDGES) return;
    int r = row[e];
    int pos = atomicAdd(&g_cur[r], 1);
    g_edge[pos] = make_int2(col[e], __float_as_int(vals[e]));
}

// ---------------------------------------------------------------------------
// tf32 helpers
// ---------------------------------------------------------------------------
__device__ __forceinline__ unsigned f2tf32(float f) {
    unsigned r;
    asm("cvt.rna.tf32.f32 %0, %1;" : "=r"(r) : "f"(f));
    return r;
}
__device__ __forceinline__ void mma_tf32(float c[4], unsigned a0, unsigned a1,
                                         unsigned a2, unsigned a3,
                                         unsigned b0, unsigned b1) {
    asm("mma.sync.aligned.m16n8k8.row.col.f32.tf32.tf32.f32 "
        "{%0,%1,%2,%3}, {%4,%5,%6,%7}, {%8,%9}, {%0,%1,%2,%3};"
        : "+f"(c[0]), "+f"(c[1]), "+f"(c[2]), "+f"(c[3])
        : "r"(a0), "r"(a1), "r"(a2), "r"(a3), "r"(b0), "r"(b1));
}

// ---------------------------------------------------------------------------
// GEMM1 (tf32 tensor cores): M=256 x N=64 block tile, 8 warps x 32 rows.
// Each warp computes two m16 tiles sharing every B fragment (halves B-LDS
// per MMA). Bank-conflict-free layouts: xs stride 36, ws stride 72.
// ---------------------------------------------------------------------------
__global__ __launch_bounds__(256) void k_gemm1(const float* __restrict__ x,
                                               const float* __restrict__ W1,
                                               const float* __restrict__ b1) {
    __shared__ unsigned xs[256][36];   // A: bank = 4*qr + qc (mod 32)
    __shared__ unsigned ws[32][72];    // B: bank = 8*qc + qr  (mod 32)
    __shared__ float b1s[64];

    int tid = threadIdx.x;
    int n0 = blockIdx.x * 256;
    if (tid < 64) b1s[tid] = b1[tid];

    int warp = tid >> 5, lane = tid & 31;
    int qr = lane >> 2, qc = lane & 3;

    float c[2][8][4];
#pragma unroll
    for (int mt = 0; mt < 2; mt++)
#pragma unroll
        for (int i = 0; i < 8; i++)
#pragma unroll
            for (int j = 0; j < 4; j++) c[mt][i][j] = 0.0f;

    // loaders: one thread per x-row (32 k per chunk); W chunk 32x64
    int wk = tid >> 3, wc = (tid & 7) * 8;
    long gxn = n0 + tid;
    bool xok = (gxn < N_NODES);
    const float* xbase = x + gxn * N_FEAT;

    for (int k0 = 0; k0 < N_FEAT; k0 += 32) {
        __syncthreads();
        if (xok) {
            const float4* xp = (const float4*)(xbase + k0);
#pragma unroll
            for (int i = 0; i < 8; i++) {
                float4 v = xp[i];
                xs[tid][i * 4 + 0] = f2tf32(v.x);
                xs[tid][i * 4 + 1] = f2tf32(v.y);
                xs[tid][i * 4 + 2] = f2tf32(v.z);
                xs[tid][i * 4 + 3] = f2tf32(v.w);
            }
        } else {
#pragma unroll
            for (int i = 0; i < 32; i++) xs[tid][i] = 0u;
        }
        {
            const float4* wp = (const float4*)(W1 + (long)(k0 + wk) * N_HID + wc);
#pragma unroll
            for (int i = 0; i < 2; i++) {
                float4 v = wp[i];
                ws[wk][wc + i * 4 + 0] = f2tf32(v.x);
                ws[wk][wc + i * 4 + 1] = f2tf32(v.y);
                ws[wk][wc + i * 4 + 2] = f2tf32(v.z);
                ws[wk][wc + i * 4 + 3] = f2tf32(v.w);
            }
        }
        __syncthreads();

        int m0 = warp * 32 + qr;          // mt=0 base row
#pragma unroll
        for (int ks = 0; ks < 4; ks++) {
            int kq = ks * 8 + qc;
            unsigned a[2][4];
#pragma unroll
            for (int mt = 0; mt < 2; mt++) {
                int m = m0 + mt * 16;
                a[mt][0] = xs[m][kq];
                a[mt][1] = xs[m + 8][kq];
                a[mt][2] = xs[m][kq + 4];
                a[mt][3] = xs[m + 8][kq + 4];
            }
#pragma unroll
            for (int nt = 0; nt < 8; nt++) {
                unsigned b0 = ws[kq][nt * 8 + qr];
                unsigned b1v = ws[kq + 4][nt * 8 + qr];
                mma_tf32(c[0][nt], a[0][0], a[0][1], a[0][2], a[0][3], b0, b1v);
                mma_tf32(c[1][nt], a[1][0], a[1][1], a[1][2], a[1][3], b0, b1v);
            }
        }
    }

    // epilogue: + bias, convert to half2, store
#pragma unroll
    for (int mt = 0; mt < 2; mt++) {
        int row0 = n0 + warp * 32 + mt * 16 + qr;
        int row1 = row0 + 8;
#pragma unroll
        for (int nt = 0; nt < 8; nt++) {
            int cc = nt * 8 + qc * 2;
            float bb0 = b1s[cc], bb1 = b1s[cc + 1];
            if (row0 < N_NODES)
                g_h0h[(long)row0 * 32 + (cc >> 1)] =
                    __floats2half2_rn(c[mt][nt][0] + bb0, c[mt][nt][1] + bb1);
            if (row1 < N_NODES)
                g_h0h[(long)row1 * 32 + (cc >> 1)] =
                    __floats2half2_rn(c[mt][nt][2] + bb0, c[mt][nt][3] + bb1);
        }
    }
}

// ---------------------------------------------------------------------------
// SpMM1 fused with ReLU + GEMM2 + bias: one warp per row, fp16 gather.
// ---------------------------------------------------------------------------
__global__ __launch_bounds__(256) void k_spmm1f(const float* __restrict__ W2,
                                                const float* __restrict__ b2) {
    __shared__ float2 w2p[N_CLS][32];   // w2p[j][l] = (W2[2l][j], W2[2l+1][j])
    __shared__ float b2s[N_CLS];
    int tid = threadIdx.x;
    for (int i = tid; i < N_CLS * 32; i += 256) {
        int l = i >> 4, j = i & 15;
        w2p[j][l] = make_float2(W2[(2 * l) * N_CLS + j], W2[(2 * l + 1) * N_CLS + j]);
    }
    if (tid < N_CLS) b2s[tid] = b2[tid];
    __syncthreads();

    int warp = tid >> 5, lane = tid & 31;
    int r = blockIdx.x * 8 + warp;
    if (r >= N_NODES) return;

    int beg = g_ptr[r], end = g_ptr[r + 1];
    float a0 = 0.0f, a1 = 0.0f;
#pragma unroll 4
    for (int e = beg; e < end; e++) {
        int2 ed = g_edge[e];
        float v = __int_as_float(ed.y);
        float2 h = __half22float2(g_h0h[(long)ed.x * 32 + lane]);
        a0 += v * h.x;
        a1 += v * h.y;
    }
    a0 = fmaxf(a0, 0.0f);
    a1 = fmaxf(a1, 0.0f);

    float p[N_CLS];
#pragma unroll
    for (int j = 0; j < N_CLS; j++) {
        float2 w = w2p[j][lane];
        p[j] = a0 * w.x + a1 * w.y;
    }
#pragma unroll
    for (int j = 0; j < N_CLS; j++) {
#pragma unroll
        for (int off = 16; off; off >>= 1)
            p[j] += __shfl_xor_sync(0xffffffffu, p[j], off);
    }
    if (lane == 0) {
        float4* o = (float4*)(g_h2 + (long)r * N_CLS);
        o[0] = make_float4(p[0] + b2s[0],  p[1] + b2s[1],  p[2] + b2s[2],  p[3] + b2s[3]);
        o[1] = make_float4(p[4] + b2s[4],  p[5] + b2s[5],  p[6] + b2s[6],  p[7] + b2s[7]);
        o[2] = make_float4(p[8] + b2s[8],  p[9] + b2s[9],  p[10] + b2s[10], p[11] + b2s[11]);
        o[3] = make_float4(p[12] + b2s[12], p[13] + b2s[13], p[14] + b2s[14], p[15] + b2s[15]);
    }
}

// ---------------------------------------------------------------------------
// SpMM2 fused with log_softmax: half-warp per row, one class per lane.
// ---------------------------------------------------------------------------
__global__ __launch_bounds__(256) void k_spmm2f(float* __restrict__ out) {
    int tid = threadIdx.x;
    int warp = tid >> 5, lane = tid & 31;
    int half = lane >> 4, l16 = lane & 15;
    int r = (blockIdx.x * 8 + warp) * 2 + half;
    if (r >= N_NODES) return;

    int beg = g_ptr[r], end = g_ptr[r + 1];
    float acc = 0.0f;
#pragma unroll 4
    for (int e = beg; e < end; e++) {
        int2 ed = g_edge[e];
        acc += __int_as_float(ed.y) * __ldg(g_h2 + (long)ed.x * N_CLS + l16);
    }
    float m = acc;
#pragma unroll
    for (int off = 8; off; off >>= 1)
        m = fmaxf(m, __shfl_xor_sync(0xffffffffu, m, off, 16));
    float s = expf(acc - m);
#pragma unroll
    for (int off = 8; off; off >>= 1)
        s += __shfl_xor_sync(0xffffffffu, s, off, 16);
    out[(long)r * N_CLS + l16] = acc - m - logf(s);
}

// ---------------------------------------------------------------------------
extern "C" void kernel_launch(void* const* d_in, const int* in_sizes, int n_in,
                              void* d_out, int out_size) {
    const float* x     = (const float*)d_in[0];
    const int*   arow  = (const int*)  d_in[1];
    const int*   acol  = (const int*)  d_in[2];
    const float* avals = (const float*)d_in[3];
    const float* W1    = (const float*)d_in[4];
    const float* b1    = (const float*)d_in[5];
    const float* W2    = (const float*)d_in[6];
    const float* b2    = (const float*)d_in[7];
    float* out = (float*)d_out;

    k_zero_cnt<<<(N_NODES + 255) / 256, 256>>>();
    k_hist<<<(N_EDGES + 255) / 256, 256>>>(arow);
    k_scan1<<<SCAN_NBLK, SCAN_BLK>>>();
    k_gemm1<<<(N_NODES + 255) / 256, 256>>>(x, W1, b1);   // 4th launch: profiled
    k_scan3<<<SCAN_NBLK, SCAN_BLK>>>();
    k_scatter<<<(N_EDGES + 255) / 256, 256>>>(arow, acol, avals);

    k_spmm1f<<<(N_NODES + 7) / 8, 256>>>(W2, b2);
    k_spmm2f<<<(N_NODES + 15) / 16, 256>>>(out);
}

// round 8
// speedup vs baseline: 1.1185x; 1.1185x over previous
#include <cuda_runtime.h>
#include <cuda_fp16.h>

#define N_NODES 100000
#define N_EDGES 1600000
#define N_FEAT  256
#define N_HID   64
#define N_CLS   16

#define SCAN_BLK  512
#define SCAN_NBLK ((N_NODES + SCAN_BLK - 1) / SCAN_BLK)   // 196

// ---------------- scratch (device globals: allocation-free, graph-safe) ----
__device__ __half2 g_h0h[N_NODES * (N_HID / 2)];  // x@W1+b1, fp16 pairs
__device__ __half  g_h2h[N_NODES * N_CLS];        // relu(spmm1)@W2+b2, fp16
__device__ int     g_cnt[N_NODES];
__device__ int     g_scan[N_NODES];
__device__ int     g_blk[SCAN_NBLK];
__device__ int     g_ptr[N_NODES + 1];
__device__ int     g_cur[N_NODES];
__device__ int2    g_edge[N_EDGES];               // {col, float_bits(val)} by row

// ---------------------------------------------------------------------------
// CSR build
// ---------------------------------------------------------------------------
__global__ void k_hist(const int* __restrict__ row) {
    int e = blockIdx.x * blockDim.x + threadIdx.x;
    if (e < N_EDGES) atomicAdd(&g_cnt[row[e]], 1);
}

__global__ __launch_bounds__(SCAN_BLK) void k_scan1() {
    __shared__ int s[SCAN_BLK];
    int i = blockIdx.x * SCAN_BLK + threadIdx.x;
    int v = (i < N_NODES) ? g_cnt[i] : 0;
    s[threadIdx.x] = v;
    __syncthreads();
    for (int off = 1; off < SCAN_BLK; off <<= 1) {
        int t = (threadIdx.x >= off) ? s[threadIdx.x - off] : 0;
        __syncthreads();
        s[threadIdx.x] += t;
        __syncthreads();
    }
    if (i < N_NODES) g_scan[i] = s[threadIdx.x];
    if (threadIdx.x == SCAN_BLK - 1) g_blk[blockIdx.x] = s[threadIdx.x];
}

__global__ __launch_bounds__(SCAN_BLK) void k_scan3() {
    __shared__ int s[SCAN_BLK];
    int t = threadIdx.x;
    s[t] = (t < SCAN_NBLK && t < (int)blockIdx.x) ? g_blk[t] : 0;
    __syncthreads();
    for (int off = SCAN_BLK / 2; off; off >>= 1) {
        if (t < off) s[t] += s[t + off];
        __syncthreads();
    }
    int blkoff = s[0];
    int i = blockIdx.x * SCAN_BLK + t;
    if (i < N_NODES) {
        int excl = g_scan[i] - g_cnt[i] + blkoff;
        g_ptr[i] = excl;
        g_cur[i] = excl;
    }
    if (i == 0) g_ptr[N_NODES] = N_EDGES;
}

__global__ void k_scatter(const int* __restrict__ row, const int* __restrict__ col,
                          const float* __restrict__ vals) {
    int e = blockIdx.x * blockDim.x + threadIdx.x;
    if (e >= N_EDGES) return;
    int r = row[e];
    int pos = atomicAdd(&g_cur[r], 1);
    g_edge[pos] = make_int2(col[e], __float_as_int(vals[e]));
}

// ---------------------------------------------------------------------------
// tf32 helpers
// ---------------------------------------------------------------------------
__device__ __forceinline__ unsigned f2tf32(float f) {
    unsigned r;
    asm("cvt.rna.tf32.f32 %0, %1;" : "=r"(r) : "f"(f));
    return r;
}
__device__ __forceinline__ void mma_tf32(float c[4], unsigned a0, unsigned a1,
                                         unsigned a2, unsigned a3,
                                         unsigned b0, unsigned b1) {
    asm("mma.sync.aligned.m16n8k8.row.col.f32.tf32.tf32.f32 "
        "{%0,%1,%2,%3}, {%4,%5,%6,%7}, {%8,%9}, {%0,%1,%2,%3};"
        : "+f"(c[0]), "+f"(c[1]), "+f"(c[2]), "+f"(c[3])
        : "r"(a0), "r"(a1), "r"(a2), "r"(a3), "r"(b0), "r"(b1));
}

// ---------------------------------------------------------------------------
// GEMM1 (tf32 tensor cores) — proven R6 version: M=128 x N=64 tile,
// conflict-free xs stride 36 / ws stride 72, fp16 epilogue.
// ---------------------------------------------------------------------------
__global__ __launch_bounds__(256) void k_gemm1(const float* __restrict__ x,
                                               const float* __restrict__ W1,
                                               const float* __restrict__ b1) {
    __shared__ unsigned xs[128][36];   // A: bank = 4*qr + qc, conflict-free
    __shared__ unsigned ws[32][72];    // B: bank = 8*qc + qr, conflict-free
    __shared__ float b1s[64];

    int tid = threadIdx.x;
    int n0 = blockIdx.x * 128;
    if (tid < 64) b1s[tid] = b1[tid];

    int warp = tid >> 5, lane = tid & 31;
    int qr = lane >> 2, qc = lane & 3;

    float c[8][4];
#pragma unroll
    for (int i = 0; i < 8; i++)
#pragma unroll
        for (int j = 0; j < 4; j++) c[i][j] = 0.0f;

    int xr = tid >> 1, xc = (tid & 1) * 16;
    int wk = tid >> 3, wc = (tid & 7) * 8;

    for (int k0 = 0; k0 < N_FEAT; k0 += 32) {
        __syncthreads();
        long gn = n0 + xr;
        if (gn < N_NODES) {
            const float4* xp = (const float4*)(x + gn * N_FEAT + k0 + xc);
#pragma unroll
            for (int i = 0; i < 4; i++) {
                float4 v = xp[i];
                xs[xr][xc + i * 4 + 0] = f2tf32(v.x);
                xs[xr][xc + i * 4 + 1] = f2tf32(v.y);
                xs[xr][xc + i * 4 + 2] = f2tf32(v.z);
                xs[xr][xc + i * 4 + 3] = f2tf32(v.w);
            }
        } else {
#pragma unroll
            for (int i = 0; i < 16; i++) xs[xr][xc + i] = 0u;
        }
        {
            const float4* wp = (const float4*)(W1 + (long)(k0 + wk) * N_HID + wc);
#pragma unroll
            for (int i = 0; i < 2; i++) {
                float4 v = wp[i];
                ws[wk][wc + i * 4 + 0] = f2tf32(v.x);
                ws[wk][wc + i * 4 + 1] = f2tf32(v.y);
                ws[wk][wc + i * 4 + 2] = f2tf32(v.z);
                ws[wk][wc + i * 4 + 3] = f2tf32(v.w);
            }
        }
        __syncthreads();

        int m = warp * 16 + qr;
#pragma unroll
        for (int ks = 0; ks < 4; ks++) {
            int kq = ks * 8 + qc;
            unsigned a0 = xs[m][kq];
            unsigned a1 = xs[m + 8][kq];
            unsigned a2 = xs[m][kq + 4];
            unsigned a3 = xs[m + 8][kq + 4];
#pragma unroll
            for (int nt = 0; nt < 8; nt++) {
                unsigned b0 = ws[kq][nt * 8 + qr];
                unsigned b1v = ws[kq + 4][nt * 8 + qr];
                mma_tf32(c[nt], a0, a1, a2, a3, b0, b1v);
            }
        }
    }

    int row0 = n0 + warp * 16 + qr;
    int row1 = row0 + 8;
#pragma unroll
    for (int nt = 0; nt < 8; nt++) {
        int cc = nt * 8 + qc * 2;
        float bb0 = b1s[cc], bb1 = b1s[cc + 1];
        if (row0 < N_NODES)
            g_h0h[(long)row0 * 32 + (cc >> 1)] =
                __floats2half2_rn(c[nt][0] + bb0, c[nt][1] + bb1);
        if (row1 < N_NODES)
            g_h0h[(long)row1 * 32 + (cc >> 1)] =
                __floats2half2_rn(c[nt][2] + bb0, c[nt][3] + bb1);
    }
}

// ---------------------------------------------------------------------------
// SpMM1 fused with ReLU + GEMM2 + bias: one warp per row, fp16 gather,
// fp16 h2 output.
// ---------------------------------------------------------------------------
__global__ __launch_bounds__(256) void k_spmm1f(const float* __restrict__ W2,
                                                const float* __restrict__ b2) {
    __shared__ float2 w2p[N_CLS][32];   // w2p[j][l] = (W2[2l][j], W2[2l+1][j])
    __shared__ float b2s[N_CLS];
    int tid = threadIdx.x;
    for (int i = tid; i < N_CLS * 32; i += 256) {
        int l = i >> 4, j = i & 15;
        w2p[j][l] = make_float2(W2[(2 * l) * N_CLS + j], W2[(2 * l + 1) * N_CLS + j]);
    }
    if (tid < N_CLS) b2s[tid] = b2[tid];
    __syncthreads();

    int warp = tid >> 5, lane = tid & 31;
    int r = blockIdx.x * 8 + warp;
    if (r >= N_NODES) return;

    int beg = g_ptr[r], end = g_ptr[r + 1];
    float a0 = 0.0f, a1 = 0.0f;
#pragma unroll 4
    for (int e = beg; e < end; e++) {
        int2 ed = g_edge[e];
        float v = __int_as_float(ed.y);
        float2 h = __half22float2(g_h0h[(long)ed.x * 32 + lane]);
        a0 += v * h.x;
        a1 += v * h.y;
    }
    a0 = fmaxf(a0, 0.0f);
    a1 = fmaxf(a1, 0.0f);

    float p[N_CLS];
#pragma unroll
    for (int j = 0; j < N_CLS; j++) {
        float2 w = w2p[j][lane];
        p[j] = a0 * w.x + a1 * w.y;
    }
#pragma unroll
    for (int j = 0; j < N_CLS; j++) {
#pragma unroll
        for (int off = 16; off; off >>= 1)
            p[j] += __shfl_xor_sync(0xffffffffu, p[j], off);
    }
    if (lane == 0) {
        __half2 hh[8];
#pragma unroll
        for (int j = 0; j < 8; j++)
            hh[j] = __floats2half2_rn(p[2 * j] + b2s[2 * j],
                                      p[2 * j + 1] + b2s[2 * j + 1]);
        uint4* o = (uint4*)(g_h2h + (long)r * N_CLS);
        o[0] = *(uint4*)&hh[0];
        o[1] = *(uint4*)&hh[4];
    }
}

// ---------------------------------------------------------------------------
// SpMM2 fused with log_softmax: half-warp per row, one class per lane,
// fp16 h2 gather (32B per edge).
// ---------------------------------------------------------------------------
__global__ __launch_bounds__(256) void k_spmm2f(float* __restrict__ out) {
    int tid = threadIdx.x;
    int warp = tid >> 5, lane = tid & 31;
    int half = lane >> 4, l16 = lane & 15;
    int r = (blockIdx.x * 8 + warp) * 2 + half;
    if (r >= N_NODES) return;

    int beg = g_ptr[r], end = g_ptr[r + 1];
    float acc = 0.0f;
#pragma unroll 4
    for (int e = beg; e < end; e++) {
        int2 ed = g_edge[e];
        acc += __int_as_float(ed.y) *
               __half2float(g_h2h[(long)ed.x * N_CLS + l16]);
    }
    float m = acc;
#pragma unroll
    for (int off = 8; off; off >>= 1)
        m = fmaxf(m, __shfl_xor_sync(0xffffffffu, m, off, 16));
    float s = expf(acc - m);
#pragma unroll
    for (int off = 8; off; off >>= 1)
        s += __shfl_xor_sync(0xffffffffu, s, off, 16);
    out[(long)r * N_CLS + l16] = acc - m - logf(s);
}

// ---------------------------------------------------------------------------
extern "C" void kernel_launch(void* const* d_in, const int* in_sizes, int n_in,
                              void* d_out, int out_size) {
    const float* x     = (const float*)d_in[0];
    const int*   arow  = (const int*)  d_in[1];
    const int*   acol  = (const int*)  d_in[2];
    const float* avals = (const float*)d_in[3];
    const float* W1    = (const float*)d_in[4];
    const float* b1    = (const float*)d_in[5];
    const float* W2    = (const float*)d_in[6];
    const float* b2    = (const float*)d_in[7];
    float* out = (float*)d_out;

    // zero the histogram via memset node (not a kernel launch)
    void* cnt_ptr = nullptr;
    cudaGetSymbolAddress(&cnt_ptr, g_cnt);
    cudaMemsetAsync(cnt_ptr, 0, N_NODES * sizeof(int));

    k_hist<<<(N_EDGES + 255) / 256, 256>>>(arow);
    k_scan1<<<SCAN_NBLK, SCAN_BLK>>>();
    k_scan3<<<SCAN_NBLK, SCAN_BLK>>>();
    k_gemm1<<<(N_NODES + 127) / 128, 256>>>(x, W1, b1);   // 4th kernel: profiled
    k_scatter<<<(N_EDGES + 255) / 256, 256>>>(arow, acol, avals);

    k_spmm1f<<<(N_NODES + 7) / 8, 256>>>(W2, b2);
    k_spmm2f<<<(N_NODES + 15) / 16, 256>>>(out);
}

// round 9
// speedup vs baseline: 1.1225x; 1.0036x over previous
#include <cuda_runtime.h>
#include <cuda_fp16.h>

#define N_NODES 100000
#define N_EDGES 1600000
#define N_FEAT  256
#define N_HID   64
#define N_CLS   16

#define SCAN_BLK  512
#define SCAN_NBLK ((N_NODES + SCAN_BLK - 1) / SCAN_BLK)   // 196

// gemm1 dynamic smem layout (words)
#define XS_STRIDE 36
#define WS_STRIDE 72
#define XS_WORDS (128 * XS_STRIDE)          // 4608 per buffer
#define WS_WORDS (32 * WS_STRIDE)           // 2304 per buffer
#define SMEM_WORDS (2 * XS_WORDS + 2 * WS_WORDS + 64)
#define SMEM_BYTES (SMEM_WORDS * 4)         // 55552

// ---------------- scratch (device globals: allocation-free, graph-safe) ----
__device__ __half2 g_h0h[N_NODES * (N_HID / 2)];  // x@W1+b1, fp16 pairs
__device__ __half  g_h2h[N_NODES * N_CLS];        // relu(spmm1)@W2+b2, fp16
__device__ int     g_cnt[N_NODES];
__device__ int     g_scan[N_NODES];
__device__ int     g_blk[SCAN_NBLK];
__device__ int     g_ptr[N_NODES + 1];
__device__ int     g_cur[N_NODES];
__device__ int2    g_edge[N_EDGES];               // {col, float_bits(val)} by row

// ---------------------------------------------------------------------------
// CSR build
// ---------------------------------------------------------------------------
__global__ void k_hist(const int* __restrict__ row) {
    int e = blockIdx.x * blockDim.x + threadIdx.x;
    if (e < N_EDGES) atomicAdd(&g_cnt[row[e]], 1);
}

__global__ __launch_bounds__(SCAN_BLK) void k_scan1() {
    __shared__ int s[SCAN_BLK];
    int i = blockIdx.x * SCAN_BLK + threadIdx.x;
    int v = (i < N_NODES) ? g_cnt[i] : 0;
    s[threadIdx.x] = v;
    __syncthreads();
    for (int off = 1; off < SCAN_BLK; off <<= 1) {
        int t = (threadIdx.x >= off) ? s[threadIdx.x - off] : 0;
        __syncthreads();
        s[threadIdx.x] += t;
        __syncthreads();
    }
    if (i < N_NODES) g_scan[i] = s[threadIdx.x];
    if (threadIdx.x == SCAN_BLK - 1) g_blk[blockIdx.x] = s[threadIdx.x];
}

__global__ __launch_bounds__(SCAN_BLK) void k_scan3() {
    __shared__ int s[SCAN_BLK];
    int t = threadIdx.x;
    s[t] = (t < SCAN_NBLK && t < (int)blockIdx.x) ? g_blk[t] : 0;
    __syncthreads();
    for (int off = SCAN_BLK / 2; off; off >>= 1) {
        if (t < off) s[t] += s[t + off];
        __syncthreads();
    }
    int blkoff = s[0];
    int i = blockIdx.x * SCAN_BLK + t;
    if (i < N_NODES) {
        int excl = g_scan[i] - g_cnt[i] + blkoff;
        g_ptr[i] = excl;
        g_cur[i] = excl;
    }
    if (i == 0) g_ptr[N_NODES] = N_EDGES;
}

__global__ void k_scatter(const int* __restrict__ row, const int* __restrict__ col,
                          const float* __restrict__ vals) {
    int e = blockIdx.x * blockDim.x + threadIdx.x;
    if (e >= N_EDGES) return;
    int r = row[e];
    int pos = atomicAdd(&g_cur[r], 1);
    g_edge[pos] = make_int2(col[e], __float_as_int(vals[e]));
}

// ---------------------------------------------------------------------------
// mma + cp.async helpers
// ---------------------------------------------------------------------------
__device__ __forceinline__ void mma_tf32(float c[4], unsigned a0, unsigned a1,
                                         unsigned a2, unsigned a3,
                                         unsigned b0, unsigned b1) {
    asm("mma.sync.aligned.m16n8k8.row.col.f32.tf32.tf32.f32 "
        "{%0,%1,%2,%3}, {%4,%5,%6,%7}, {%8,%9}, {%0,%1,%2,%3};"
        : "+f"(c[0]), "+f"(c[1]), "+f"(c[2]), "+f"(c[3])
        : "r"(a0), "r"(a1), "r"(a2), "r"(a3), "r"(b0), "r"(b1));
}

__device__ __forceinline__ void cp16(unsigned* dst_smem, const void* src, bool pred) {
    unsigned saddr = (unsigned)__cvta_generic_to_shared(dst_smem);
    int sz = pred ? 16 : 0;    // sz=0 -> zero-fill, no global read
    asm volatile("cp.async.cg.shared.global [%0], [%1], 16, %2;\n"
                 :: "r"(saddr), "l"(src), "r"(sz));
}
__device__ __forceinline__ void cp_commit() {
    asm volatile("cp.async.commit_group;\n");
}
__device__ __forceinline__ void cp_wait_all() {
    asm volatile("cp.async.wait_group 0;\n");
}

// ---------------------------------------------------------------------------
// GEMM1 (tf32 tensor cores, cp.async double-buffered pipeline).
// M=128 x N=64 tile, K-chunks of 32, raw fp32 bits fed to tf32 MMA.
// Conflict-free layouts: xs stride 36, ws stride 72.
// ---------------------------------------------------------------------------
__global__ __launch_bounds__(256) void k_gemm1(const float* __restrict__ x,
                                               const float* __restrict__ W1,
                                               const float* __restrict__ b1) {
    extern __shared__ unsigned sm[];
    unsigned* xsb[2] = { sm, sm + XS_WORDS };
    unsigned* wsb[2] = { sm + 2 * XS_WORDS, sm + 2 * XS_WORDS + WS_WORDS };
    float* b1s = (float*)(sm + 2 * XS_WORDS + 2 * WS_WORDS);

    int tid = threadIdx.x;
    int n0 = blockIdx.x * 128;
    if (tid < 64) b1s[tid] = b1[tid];

    int warp = tid >> 5, lane = tid & 31;
    int qr = lane >> 2, qc = lane & 3;

    // loader mappings
    int xr = tid >> 1, xc = (tid & 1) * 16;
    long gn = n0 + xr;
    bool xok = (gn < N_NODES);
    const float* xsrc = x + (xok ? gn : 0) * N_FEAT + xc;
    int wk = tid >> 3, wc = (tid & 7) * 8;
    const float* wsrc = W1 + (long)wk * N_HID + wc;
    unsigned* xd_base0 = xsb[0] + xr * XS_STRIDE + xc;
    unsigned* xd_base1 = xsb[1] + xr * XS_STRIDE + xc;
    unsigned* wd_base0 = wsb[0] + wk * WS_STRIDE + wc;
    unsigned* wd_base1 = wsb[1] + wk * WS_STRIDE + wc;

    // prologue: issue chunk 0 into buffer 0
    {
#pragma unroll
        for (int i = 0; i < 4; i++) cp16(xd_base0 + i * 4, xsrc + i * 4, xok);
#pragma unroll
        for (int i = 0; i < 2; i++) cp16(wd_base0 + i * 4, wsrc + i * 4, true);
        cp_commit();
    }

    float c[8][4];
#pragma unroll
    for (int i = 0; i < 8; i++)
#pragma unroll
        for (int j = 0; j < 4; j++) c[i][j] = 0.0f;

    int m = warp * 16 + qr;

    const int NCHUNK = N_FEAT / 32;   // 8
    for (int ch = 0; ch < NCHUNK; ch++) {
        int cur = ch & 1;
        cp_wait_all();        // chunk ch's copies (this thread's) complete
        __syncthreads();      // all threads' copies visible; all done with ch-1

        // issue chunk ch+1 into the other buffer (overlaps MMAs below)
        if (ch + 1 < NCHUNK) {
            int k0 = (ch + 1) * 32;
            unsigned* xd = cur ? xd_base0 : xd_base1;
            unsigned* wd = cur ? wd_base0 : wd_base1;
#pragma unroll
            for (int i = 0; i < 4; i++) cp16(xd + i * 4, xsrc + k0 + i * 4, xok);
#pragma unroll
            for (int i = 0; i < 2; i++)
                cp16(wd + i * 4, wsrc + (long)k0 * N_HID + i * 4, true);
            cp_commit();
        }

        // MMAs on current buffer
        unsigned* X = xsb[cur];
        unsigned* W = wsb[cur];
#pragma unroll
        for (int ks = 0; ks < 4; ks++) {
            int kq = ks * 8 + qc;
            unsigned a0 = X[m * XS_STRIDE + kq];
            unsigned a1 = X[(m + 8) * XS_STRIDE + kq];
            unsigned a2 = X[m * XS_STRIDE + kq + 4];
            unsigned a3 = X[(m + 8) * XS_STRIDE + kq + 4];
#pragma unroll
            for (int nt = 0; nt < 8; nt++) {
                unsigned b0 = W[kq * WS_STRIDE + nt * 8 + qr];
                unsigned b1v = W[(kq + 4) * WS_STRIDE + nt * 8 + qr];
                mma_tf32(c[nt], a0, a1, a2, a3, b0, b1v);
            }
        }
    }

    // epilogue: + bias, convert to half2, store
    int row0 = n0 + warp * 16 + qr;
    int row1 = row0 + 8;
#pragma unroll
    for (int nt = 0; nt < 8; nt++) {
        int cc = nt * 8 + qc * 2;
        float bb0 = b1s[cc], bb1 = b1s[cc + 1];
        if (row0 < N_NODES)
            g_h0h[(long)row0 * 32 + (cc >> 1)] =
                __floats2half2_rn(c[nt][0] + bb0, c[nt][1] + bb1);
        if (row1 < N_NODES)
            g_h0h[(long)row1 * 32 + (cc >> 1)] =
                __floats2half2_rn(c[nt][2] + bb0, c[nt][3] + bb1);
    }
}

// ---------------------------------------------------------------------------
// SpMM1 fused with ReLU + GEMM2 + bias: one warp per row, fp16 gather,
// fp16 h2 output.
// ---------------------------------------------------------------------------
__global__ __launch_bounds__(256) void k_spmm1f(const float* __restrict__ W2,
                                                const float* __restrict__ b2) {
    __shared__ float2 w2p[N_CLS][32];   // w2p[j][l] = (W2[2l][j], W2[2l+1][j])
    __shared__ float b2s[N_CLS];
    int tid = threadIdx.x;
    for (int i = tid; i < N_CLS * 32; i += 256) {
        int l = i >> 4, j = i & 15;
        w2p[j][l] = make_float2(W2[(2 * l) * N_CLS + j], W2[(2 * l + 1) * N_CLS + j]);
    }
    if (tid < N_CLS) b2s[tid] = b2[tid];
    __syncthreads();

    int warp = tid >> 5, lane = tid & 31;
    int r = blockIdx.x * 8 + warp;
    if (r >= N_NODES) return;

    int beg = g_ptr[r], end = g_ptr[r + 1];
    float a0 = 0.0f, a1 = 0.0f;
#pragma unroll 4
    for (int e = beg; e < end; e++) {
        int2 ed = g_edge[e];
        float v = __int_as_float(ed.y);
        float2 h = __half22float2(g_h0h[(long)ed.x * 32 + lane]);
        a0 += v * h.x;
        a1 += v * h.y;
    }
    a0 = fmaxf(a0, 0.0f);
    a1 = fmaxf(a1, 0.0f);

    float p[N_CLS];
#pragma unroll
    for (int j = 0; j < N_CLS; j++) {
        float2 w = w2p[j][lane];
        p[j] = a0 * w.x + a1 * w.y;
    }
#pragma unroll
    for (int j = 0; j < N_CLS; j++) {
#pragma unroll
        for (int off = 16; off; off >>= 1)
            p[j] += __shfl_xor_sync(0xffffffffu, p[j], off);
    }
    if (lane == 0) {
        __half2 hh[8];
#pragma unroll
        for (int j = 0; j < 8; j++)
            hh[j] = __floats2half2_rn(p[2 * j] + b2s[2 * j],
                                      p[2 * j + 1] + b2s[2 * j + 1]);
        uint4* o = (uint4*)(g_h2h + (long)r * N_CLS);
        o[0] = *(uint4*)&hh[0];
        o[1] = *(uint4*)&hh[4];
    }
}

// ---------------------------------------------------------------------------
// SpMM2 fused with log_softmax: half-warp per row, one class per lane.
// ---------------------------------------------------------------------------
__global__ __launch_bounds__(256) void k_spmm2f(float* __restrict__ out) {
    int tid = threadIdx.x;
    int warp = tid >> 5, lane = tid & 31;
    int half = lane >> 4, l16 = lane & 15;
    int r = (blockIdx.x * 8 + warp) * 2 + half;
    if (r >= N_NODES) return;

    int beg = g_ptr[r], end = g_ptr[r + 1];
    float acc = 0.0f;
#pragma unroll 4
    for (int e = beg; e < end; e++) {
        int2 ed = g_edge[e];
        acc += __int_as_float(ed.y) *
               __half2float(g_h2h[(long)ed.x * N_CLS + l16]);
    }
    float m = acc;
#pragma unroll
    for (int off = 8; off; off >>= 1)
        m = fmaxf(m, __shfl_xor_sync(0xffffffffu, m, off, 16));
    float s = expf(acc - m);
#pragma unroll
    for (int off = 8; off; off >>= 1)
        s += __shfl_xor_sync(0xffffffffu, s, off, 16);
    out[(long)r * N_CLS + l16] = acc - m - logf(s);
}

// ---------------------------------------------------------------------------
extern "C" void kernel_launch(void* const* d_in, const int* in_sizes, int n_in,
                              void* d_out, int out_size) {
    const float* x     = (const float*)d_in[0];
    const int*   arow  = (const int*)  d_in[1];
    const int*   acol  = (const int*)  d_in[2];
    const float* avals = (const float*)d_in[3];
    const float* W1    = (const float*)d_in[4];
    const float* b1    = (const float*)d_in[5];
    const float* W2    = (const float*)d_in[6];
    const float* b2    = (const float*)d_in[7];
    float* out = (float*)d_out;

    // allow >48KB dynamic smem for gemm1 (host attribute set, capture-safe)
    static bool attr_done = false;
    if (!attr_done) {
        cudaFuncSetAttribute(k_gemm1, cudaFuncAttributeMaxDynamicSharedMemorySize,
                             SMEM_BYTES);
        attr_done = true;
    }

    void* cnt_ptr = nullptr;
    cudaGetSymbolAddress(&cnt_ptr, g_cnt);
    cudaMemsetAsync(cnt_ptr, 0, N_NODES * sizeof(int));

    k_hist<<<(N_EDGES + 255) / 256, 256>>>(arow);
    k_scan1<<<SCAN_NBLK, SCAN_BLK>>>();
    k_scan3<<<SCAN_NBLK, SCAN_BLK>>>();
    k_gemm1<<<(N_NODES + 127) / 128, 256, SMEM_BYTES>>>(x, W1, b1);  // 4th kernel
    k_scatter<<<(N_EDGES + 255) / 256, 256>>>(arow, acol, avals);

    k_spmm1f<<<(N_NODES + 7) / 8, 256>>>(W2, b2);
    k_spmm2f<<<(N_NODES + 15) / 16, 256>>>(out);
}